// round 1
// baseline (speedup 1.0000x reference)
#include <cuda_runtime.h>

// MPSLayer: BATCH=128, N_SITES=64 (two halves of 32), D_BOND=128, N_OUTPUT=10, DIM=2
//
// Algorithm:
//   A_l = x0*W0_l + x1*W1_l  (linear in 2 basis matrices per site)
//   Tree levels 0 and 1 are computed in a batch-independent basis:
//     B0[h,p,(s0,s1)] = W_{s0}[h,2p] @ W_{s1}[h,2p+1]              (128 matmuls)
//     B1[h,q,t]       = B0[h,2q,t>>2] @ B0[h,2q+1,t&3]            (256 matmuls)
//   Per-batch level-1 matrices are 16-term weighted sums of B1 (coeffs are
//   products of 4 input scalars). Then batched tree levels 2..4, the
//   R@L product, and the trace against `middle`.
//   Total: 2304 matmuls of 128^3 (= 9.66 GFLOP) vs 33.8 GFLOP naive.

#define D      128
#define NB     128
#define NHALF  32
#define NOUT   10
#define MATSZ  (D * D)   // 16384

// ---- scratch (static device globals; no runtime allocation) ----
__device__ float g_B0[2 * 16 * 4 * MATSZ];       //   8 MB  basis level 0
__device__ float g_B1[2 * 8 * 16 * MATSZ];       //  16 MB  basis level 1
__device__ float g_coef[NB * 2 * 8 * 16];        // 128 KB  per-batch coefficients
__device__ float g_M2[NB * 2 * 8 * MATSZ];       // 134 MB  materialized level-1 per batch
__device__ float g_L2[NB * 2 * 4 * MATSZ];       //  64 MB
__device__ float g_L3[NB * 2 * 2 * MATSZ];       //  32 MB
__device__ float g_L4[NB * 2 * MATSZ];           //  16 MB
__device__ float g_P [NB * MATSZ];               //   8 MB  P_b = R_b @ L_b

// ============================================================================
// 128x128x128 fp32 SGEMM, one CTA (256 threads) per matmul.
// 16x16 thread grid, 8x8 register tile per thread, BK=8 double-buffered smem.
// ============================================================================
__device__ __forceinline__ void sgemm128(const float* __restrict__ A,
                                         const float* __restrict__ B,
                                         float* __restrict__ C) {
    __shared__ float As[2][8][128];   // As[buf][k][i]  (A stored transposed)
    __shared__ float Bs[2][8][128];   // Bs[buf][k][j]

    const int tid = threadIdx.x;
    const int ti  = tid >> 4;          // 0..15 row group
    const int tj  = tid & 15;          // 0..15 col group
    const int ar  = tid >> 1;          // A row this thread loads (0..127)
    const int ac  = (tid & 1) << 2;    // A col offset within K-tile {0,4}
    const int br  = tid >> 5;          // B row within K-tile (0..7)
    const int bc  = (tid & 31) << 2;   // B col (0..124 step 4)

    float acc[8][8];
#pragma unroll
    for (int i = 0; i < 8; i++)
#pragma unroll
        for (int j = 0; j < 8; j++) acc[i][j] = 0.0f;

    // prologue: fill buffer 0
    float4 av = *(const float4*)(A + ar * 128 + ac);
    float4 bv = *(const float4*)(B + br * 128 + bc);
    As[0][ac + 0][ar] = av.x;
    As[0][ac + 1][ar] = av.y;
    As[0][ac + 2][ar] = av.z;
    As[0][ac + 3][ar] = av.w;
    *(float4*)&Bs[0][br][bc] = bv;
    __syncthreads();

#pragma unroll
    for (int k0 = 0; k0 < 128; k0 += 8) {
        const int cur = (k0 >> 3) & 1;
        const int nxt = cur ^ 1;
        const bool more = (k0 + 8) < 128;
        if (more) {  // prefetch next K-tile from global
            av = *(const float4*)(A + ar * 128 + (k0 + 8) + ac);
            bv = *(const float4*)(B + (k0 + 8 + br) * 128 + bc);
        }
#pragma unroll
        for (int k = 0; k < 8; k++) {
            float a0[8], b0[8];
            *(float4*)(a0)     = *(const float4*)&As[cur][k][ti * 8];
            *(float4*)(a0 + 4) = *(const float4*)&As[cur][k][ti * 8 + 4];
            *(float4*)(b0)     = *(const float4*)&Bs[cur][k][tj * 8];
            *(float4*)(b0 + 4) = *(const float4*)&Bs[cur][k][tj * 8 + 4];
#pragma unroll
            for (int i = 0; i < 8; i++)
#pragma unroll
                for (int j = 0; j < 8; j++)
                    acc[i][j] = fmaf(a0[i], b0[j], acc[i][j]);
        }
        if (more) {
            As[nxt][ac + 0][ar] = av.x;
            As[nxt][ac + 1][ar] = av.y;
            As[nxt][ac + 2][ar] = av.z;
            As[nxt][ac + 3][ar] = av.w;
            *(float4*)&Bs[nxt][br][bc] = bv;
        }
        __syncthreads();
    }

#pragma unroll
    for (int i = 0; i < 8; i++) {
        float4 v0 = make_float4(acc[i][0], acc[i][1], acc[i][2], acc[i][3]);
        float4 v1 = make_float4(acc[i][4], acc[i][5], acc[i][6], acc[i][7]);
        *(float4*)(C + (ti * 8 + i) * 128 + tj * 8)     = v0;
        *(float4*)(C + (ti * 8 + i) * 128 + tj * 8 + 4) = v1;
    }
}

// ============================================================================
// Level kernels (thin wrappers decoding blockIdx -> operand pointers)
// ============================================================================

// Basis level 0: 128 matmuls. m = h*64 + p*4 + a, a = s0*2+s1
__global__ __launch_bounds__(256, 2)
void k_basis0(const float* __restrict__ left, const float* __restrict__ right) {
    const int m = blockIdx.x;
    const int h = m >> 6;
    const int p = (m >> 2) & 15;
    const int a = m & 3;
    const int s0 = a >> 1, s1 = a & 1;
    const float* W = h ? right : left;
    const float* Am = W + (size_t)(s0 * NHALF + 2 * p) * MATSZ;
    const float* Bm = W + (size_t)(s1 * NHALF + 2 * p + 1) * MATSZ;
    float* Cm = g_B0 + (size_t)m * MATSZ;
    sgemm128(Am, Bm, Cm);
}

// Basis level 1: 256 matmuls. m = (h*8+q)*16 + t, t = a*4 + b
__global__ __launch_bounds__(256, 2)
void k_basis1() {
    const int m = blockIdx.x;
    const int h = m >> 7;
    const int q = (m >> 4) & 7;
    const int t = m & 15;
    const int a = t >> 2, b = t & 3;
    const float* Am = g_B0 + (size_t)((h * 16 + 2 * q) * 4 + a) * MATSZ;
    const float* Bm = g_B0 + (size_t)((h * 16 + 2 * q + 1) * 4 + b) * MATSZ;
    float* Cm = g_B1 + (size_t)m * MATSZ;
    sgemm128(Am, Bm, Cm);
}

// Coefficients: c[b,h,q,t] = prod of 4 input scalars for sites h*32+4q..+3
__global__ void k_coef(const float* __restrict__ inputs) {
    const int b = blockIdx.x;
    const int tid = threadIdx.x;      // 256 = 2*8*16
    const int h = tid >> 7;
    const int q = (tid >> 4) & 7;
    const int t = tid & 15;
    const int base = h * NHALF + q * 4;
    const float c = inputs[(b * 64 + base + 0) * 2 + ((t >> 3) & 1)]
                  * inputs[(b * 64 + base + 1) * 2 + ((t >> 2) & 1)]
                  * inputs[(b * 64 + base + 2) * 2 + ((t >> 1) & 1)]
                  * inputs[(b * 64 + base + 3) * 2 + (t & 1)];
    g_coef[b * 256 + tid] = c;
}

// Materialize level-1 per-batch matrices: M2[b,hq,e] = sum_t c[b,hq,t]*B1[hq,t,e]
// One element per thread, loop over all 128 batches with B1 values in registers.
__global__ __launch_bounds__(256)
void k_mat() {
    const int hq = blockIdx.y;                       // 0..15
    const int e  = blockIdx.x * 256 + threadIdx.x;   // 0..16383

    __shared__ float sc[NB][16];
    for (int i = threadIdx.x; i < NB * 16; i += 256) {
        const int b = i >> 4, t = i & 15;
        sc[b][t] = g_coef[b * 256 + hq * 16 + t];
    }
    __syncthreads();

    float v[16];
    const float* src = g_B1 + (size_t)hq * 16 * MATSZ + e;
#pragma unroll
    for (int t = 0; t < 16; t++) v[t] = src[(size_t)t * MATSZ];

#pragma unroll 4
    for (int b = 0; b < NB; b++) {
        float4 c0 = *(const float4*)&sc[b][0];
        float4 c1 = *(const float4*)&sc[b][4];
        float4 c2 = *(const float4*)&sc[b][8];
        float4 c3 = *(const float4*)&sc[b][12];
        float s = c0.x * v[0];
        s = fmaf(c0.y, v[1],  s); s = fmaf(c0.z, v[2],  s); s = fmaf(c0.w, v[3],  s);
        s = fmaf(c1.x, v[4],  s); s = fmaf(c1.y, v[5],  s); s = fmaf(c1.z, v[6],  s);
        s = fmaf(c1.w, v[7],  s); s = fmaf(c2.x, v[8],  s); s = fmaf(c2.y, v[9],  s);
        s = fmaf(c2.z, v[10], s); s = fmaf(c2.w, v[11], s); s = fmaf(c3.x, v[12], s);
        s = fmaf(c3.y, v[13], s); s = fmaf(c3.z, v[14], s); s = fmaf(c3.w, v[15], s);
        g_M2[((size_t)b * 16 + hq) * MATSZ + e] = s;
    }
}

// Batched level 2: 1024 matmuls. m = b*8 + h*4 + r
__global__ __launch_bounds__(256, 2)
void k_l2() {
    const int m = blockIdx.x;
    const int b = m >> 3;
    const int h = (m >> 2) & 1;
    const int r = m & 3;
    const float* Am = g_M2 + (size_t)(b * 16 + h * 8 + 2 * r) * MATSZ;
    const float* Bm = g_M2 + (size_t)(b * 16 + h * 8 + 2 * r + 1) * MATSZ;
    float* Cm = g_L2 + (size_t)(b * 8 + h * 4 + r) * MATSZ;
    sgemm128(Am, Bm, Cm);
}

// Batched level 3: 512 matmuls. m = b*4 + h*2 + r
__global__ __launch_bounds__(256, 2)
void k_l3() {
    const int m = blockIdx.x;
    const int b = m >> 2;
    const int h = (m >> 1) & 1;
    const int r = m & 1;
    const float* Am = g_L2 + (size_t)(b * 8 + h * 4 + 2 * r) * MATSZ;
    const float* Bm = g_L2 + (size_t)(b * 8 + h * 4 + 2 * r + 1) * MATSZ;
    float* Cm = g_L3 + (size_t)(b * 4 + h * 2 + r) * MATSZ;
    sgemm128(Am, Bm, Cm);
}

// Batched level 4: 256 matmuls. m = b*2 + h
__global__ __launch_bounds__(256, 2)
void k_l4() {
    const int m = blockIdx.x;
    const int b = m >> 1;
    const int h = m & 1;
    const float* Am = g_L3 + (size_t)(b * 4 + h * 2 + 0) * MATSZ;
    const float* Bm = g_L3 + (size_t)(b * 4 + h * 2 + 1) * MATSZ;
    float* Cm = g_L4 + (size_t)(b * 2 + h) * MATSZ;
    sgemm128(Am, Bm, Cm);
}

// P_b = R_b @ L_b : 128 matmuls
__global__ __launch_bounds__(256, 2)
void k_prod() {
    const int b = blockIdx.x;
    const float* Am = g_L4 + (size_t)(b * 2 + 1) * MATSZ;  // R
    const float* Bm = g_L4 + (size_t)(b * 2 + 0) * MATSZ;  // L
    float* Cm = g_P + (size_t)b * MATSZ;
    sgemm128(Am, Bm, Cm);
}

// out[b,c] = sum_{j,k} middle[c,j,k] * P[b,k,j]
__global__ __launch_bounds__(256)
void k_final(const float* __restrict__ middle, float* __restrict__ out) {
    const int b = blockIdx.x;
    const int tid = threadIdx.x;
    float part[NOUT];
#pragma unroll
    for (int c = 0; c < NOUT; c++) part[c] = 0.0f;

    const float* Pb = g_P + (size_t)b * MATSZ;
    for (int e = tid; e < MATSZ; e += 256) {
        const int k = e >> 7;
        const int j = e & 127;
        const float p = Pb[e];
#pragma unroll
        for (int c = 0; c < NOUT; c++)
            part[c] = fmaf(middle[c * MATSZ + j * 128 + k], p, part[c]);
    }

    __shared__ float red[256];
#pragma unroll
    for (int c = 0; c < NOUT; c++) {
        red[tid] = part[c];
        __syncthreads();
        for (int s = 128; s > 0; s >>= 1) {
            if (tid < s) red[tid] += red[tid + s];
            __syncthreads();
        }
        if (tid == 0) out[b * NOUT + c] = red[0];
        __syncthreads();
    }
}

// ============================================================================
extern "C" void kernel_launch(void* const* d_in, const int* in_sizes, int n_in,
                              void* d_out, int out_size) {
    const float* inputs = (const float*)d_in[0];  // (128, 64, 2)
    const float* left   = (const float*)d_in[1];  // (2, 32, 128, 128)
    const float* right  = (const float*)d_in[2];  // (2, 32, 128, 128)
    const float* middle = (const float*)d_in[3];  // (10, 128, 128)
    float* out = (float*)d_out;                   // (128, 10)

    k_coef  <<<128,  256>>>(inputs);
    k_basis0<<<128,  256>>>(left, right);
    k_basis1<<<256,  256>>>();
    k_mat   <<<dim3(64, 16), 256>>>();
    k_l2    <<<1024, 256>>>();
    k_l3    <<<512,  256>>>();
    k_l4    <<<256,  256>>>();
    k_prod  <<<128,  256>>>();
    k_final <<<128,  256>>>(middle, out);
}

// round 3
// speedup vs baseline: 1.6033x; 1.6033x over previous
#include <cuda_runtime.h>
#include <cuda_bf16.h>
#include <cstdint>

// MPSLayer: BATCH=128, two halves of 32 sites, D_BOND=128, NOUT=10.
// Basis trick cuts work to 2304 matmuls of 128^3. All matmuls run on tensor
// cores via mma.sync m16n8k16 bf16 (sm_80 PTX -> HMMA on sm_103a; tcgen05 is
// not compilable under the harness's compute_103 ptxas pass).
// fp32 accuracy via 3-term bf16 hi/lo split accumulated in fp32 registers:
//   A*B ~= Ahi*Bhi + Ahi*Blo + Alo*Bhi   (drops only lo*lo ~ 2^-16 rel)
// mma computes D[m,n] = sum_k A[m,k] * Bst[n,k]  (Bst = B^T stored row-major),
// so producers store odd-tree-position outputs TRANSPOSED in the epilogue.
// Per matrix: hi plane (16384 bf16) then lo plane (+PLANE).

#define D      128
#define NB     128
#define NOUT   10
#define PLANE  16384
#define MAT2   32768      // hi+lo planes in bf16 elements

// ---------------- static scratch ----------------
__device__ __nv_bfloat16 g_Wc[128 * MAT2];     //   8 MB weights (odd sites transposed)
__device__ __nv_bfloat16 g_B0[128 * MAT2];     //   8 MB basis level 0
__device__ float         g_B1[256 * PLANE];    //  16 MB basis level 1 (fp32)
__device__ float         g_coef[NB * 256];     // 128 KB
__device__ __nv_bfloat16 g_M2[2048 * MAT2];    // 128 MB materialized level-1
__device__ __nv_bfloat16 g_L2[1024 * MAT2];    //  64 MB
__device__ __nv_bfloat16 g_L3[512 * MAT2];     //  32 MB
__device__ __nv_bfloat16 g_L4[256 * MAT2];     //  16 MB
__device__ float         g_P [NB * PLANE];     //   8 MB P_b = R_b @ L_b

// ---------------- smem layout ----------------
// 4 operand planes, each 128 rows x 136 bf16 (272B row stride, conflict-free
// ldmatrix). Epilogue reuses plane area as a 128 x 129 fp32 tile.
#define ROWB     272
#define PLANE_SM 34816
#define SM_BYTES (4 * PLANE_SM)   // 139264

__device__ __forceinline__ uint32_t smem_u32(const void* p) {
    uint32_t a;
    asm("{ .reg .u64 t; cvta.to.shared.u64 t, %1; cvt.u32.u64 %0, t; }" : "=r"(a) : "l"(p));
    return a;
}

#define LDM_X4(r0, r1, r2, r3, a)                                              \
    asm volatile("ldmatrix.sync.aligned.m8n8.x4.shared.b16 {%0,%1,%2,%3}, [%4];" \
        : "=r"(r0), "=r"(r1), "=r"(r2), "=r"(r3) : "r"(a))

#define MMA_BF16(d, a, b0, b1)                                                 \
    asm volatile("mma.sync.aligned.m16n8k16.row.col.f32.bf16.bf16.f32 "        \
        "{%0,%1,%2,%3}, {%4,%5,%6,%7}, {%8,%9}, {%0,%1,%2,%3};"                \
        : "+f"((d)[0]), "+f"((d)[1]), "+f"((d)[2]), "+f"((d)[3])               \
        : "r"((a)[0]), "r"((a)[1]), "r"((a)[2]), "r"((a)[3]), "r"(b0), "r"(b1))

// ============================================================================
// 128x128x128 tensor-core GEMM, 3-term bf16 split, fp32 accumulate.
// 256 threads = 8 warps; warp tile 32(m) x 64(n) = 2x8 m16n8k16 fragments.
// mode: 0 = bf16 hi/lo output, 1 = fp32 output. transpose: store C^T.
// ============================================================================
__device__ __forceinline__ void gemm_mma(
    const __nv_bfloat16* __restrict__ A,     // hi plane; lo at +PLANE
    const __nv_bfloat16* __restrict__ B,     // hi plane; lo at +PLANE
    float* __restrict__ Cf_g,
    __nv_bfloat16* __restrict__ Cb_g,
    int mode, int transpose)
{
    extern __shared__ char smem[];
    const int tid  = threadIdx.x;
    const int wid  = tid >> 5;
    const int lane = tid & 31;

    // ---- stage operands: 4 planes (Ahi, Alo, Bhi, Blo) into padded smem ----
    {
        const __nv_bfloat16* srcs[4] = { A, A + PLANE, B, B + PLANE };
#pragma unroll
        for (int pl = 0; pl < 4; pl++) {
            const float4* s = (const float4*)srcs[pl];
            char* dst = smem + pl * PLANE_SM;
            for (int i = tid; i < 2048; i += 256) {
                const int r = i >> 4, c = i & 15;
                *(float4*)(dst + r * ROWB + c * 16) = s[i];
            }
        }
    }
    __syncthreads();

    const uint32_t smb = smem_u32(smem);
    const uint32_t sAhi = smb;
    const uint32_t sAlo = smb + PLANE_SM;
    const uint32_t sBhi = smb + 2 * PLANE_SM;
    const uint32_t sBlo = smb + 3 * PLANE_SM;

    const int m0 = (wid & 3) << 5;   // 0,32,64,96
    const int n0 = (wid >> 2) << 6;  // 0,64
    const int lr = lane & 15;        // ldmatrix row within 16-row tile
    const int lk = (lane >> 4) << 4; // 0 or 16 bytes (k-half * 8 elems * 2B)

    float acc[2][8][4];
#pragma unroll
    for (int mt = 0; mt < 2; mt++)
#pragma unroll
        for (int nt = 0; nt < 8; nt++)
#pragma unroll
            for (int q = 0; q < 4; q++) acc[mt][nt][q] = 0.0f;

#pragma unroll
    for (int k0 = 0; k0 < 128; k0 += 16) {
        const uint32_t kb = (uint32_t)(k0 * 2 + lk);
        uint32_t ah[2][4], al[2][4], bh[4][4], bl[4][4];
#pragma unroll
        for (int mt = 0; mt < 2; mt++) {
            const uint32_t ra = (uint32_t)(m0 + mt * 16 + lr) * ROWB + kb;
            LDM_X4(ah[mt][0], ah[mt][1], ah[mt][2], ah[mt][3], sAhi + ra);
            LDM_X4(al[mt][0], al[mt][1], al[mt][2], al[mt][3], sAlo + ra);
        }
#pragma unroll
        for (int np = 0; np < 4; np++) {
            const uint32_t rb = (uint32_t)(n0 + np * 16 + lr) * ROWB + kb;
            LDM_X4(bh[np][0], bh[np][1], bh[np][2], bh[np][3], sBhi + rb);
            LDM_X4(bl[np][0], bl[np][1], bl[np][2], bl[np][3], sBlo + rb);
        }
#pragma unroll
        for (int mt = 0; mt < 2; mt++)
#pragma unroll
            for (int nt = 0; nt < 8; nt++) {
                const int g = nt >> 1, s = nt & 1;
                MMA_BF16(acc[mt][nt], ah[mt], bh[g][s], bh[g][s + 2]);
                MMA_BF16(acc[mt][nt], ah[mt], bl[g][s], bl[g][s + 2]);
                MMA_BF16(acc[mt][nt], al[mt], bh[g][s], bh[g][s + 2]);
            }
    }

    // ---- epilogue: park accum in smem fp32 tile (stride 129), then store ----
    __syncthreads();   // operand smem dead; safe to overwrite
    float* Cf = (float*)smem;
    {
        const int cr = lane >> 2;
        const int cc = (lane & 3) << 1;
#pragma unroll
        for (int mt = 0; mt < 2; mt++)
#pragma unroll
            for (int nt = 0; nt < 8; nt++) {
                const int r = m0 + mt * 16 + cr;
                const int c = n0 + nt * 8 + cc;
                Cf[r * 129 + c]           = acc[mt][nt][0];
                Cf[r * 129 + c + 1]       = acc[mt][nt][1];
                Cf[(r + 8) * 129 + c]     = acc[mt][nt][2];
                Cf[(r + 8) * 129 + c + 1] = acc[mt][nt][3];
            }
    }
    __syncthreads();

    for (int i = tid; i < 8192; i += 256) {
        const int e = i << 1;
        const int r = e >> 7, c = e & 127;
        float v0, v1;
        if (transpose) { v0 = Cf[c * 129 + r]; v1 = Cf[(c + 1) * 129 + r]; }
        else           { v0 = Cf[r * 129 + c]; v1 = Cf[r * 129 + c + 1];  }
        if (mode == 1) {
            *(float2*)(Cf_g + e) = make_float2(v0, v1);
        } else {
            __nv_bfloat162 hh, ll;
            hh.x = __float2bfloat16(v0);
            hh.y = __float2bfloat16(v1);
            ll.x = __float2bfloat16(v0 - __bfloat162float(hh.x));
            ll.y = __float2bfloat16(v1 - __bfloat162float(hh.y));
            *(uint32_t*)(Cb_g + e)         = *(uint32_t*)&hh;
            *(uint32_t*)(Cb_g + PLANE + e) = *(uint32_t*)&ll;
        }
    }
}

// ============================================================================
// Level kernels
// ============================================================================

// Convert fp32 weights -> hi/lo bf16; odd sites stored transposed (B-operands).
__global__ __launch_bounds__(256)
void k_conv(const float* __restrict__ left, const float* __restrict__ right) {
    const int m = blockIdx.x;               // h*64 + s*32 + site
    const int h = m >> 6;
    const int s = (m >> 5) & 1;
    const int site = m & 31;
    const float* src = (h ? right : left) + (size_t)(s * 32 + site) * PLANE;
    __nv_bfloat16* dst = g_Wc + (size_t)m * MAT2;
    const bool tr = site & 1;
    for (int e = threadIdx.x; e < PLANE; e += 256) {
        const float v = tr ? src[(e & 127) * 128 + (e >> 7)] : src[e];
        const __nv_bfloat16 hi = __float2bfloat16(v);
        dst[e] = hi;
        dst[PLANE + e] = __float2bfloat16(v - __bfloat162float(hi));
    }
}

// Basis level 0: 128 matmuls. m = h*64 + p*4 + (s0*2+s1); transpose when p odd.
__global__ __launch_bounds__(256)
void k_basis0() {
    const int m = blockIdx.x;
    const int h = m >> 6, p = (m >> 2) & 15, a = m & 3;
    const int s0 = a >> 1, s1 = a & 1;
    gemm_mma(g_Wc + (size_t)(h * 64 + s0 * 32 + 2 * p) * MAT2,
             g_Wc + (size_t)(h * 64 + s1 * 32 + 2 * p + 1) * MAT2,
             nullptr, g_B0 + (size_t)m * MAT2, 0, p & 1);
}

// Basis level 1: 256 matmuls -> fp32, transposed when q odd.
__global__ __launch_bounds__(256)
void k_basis1() {
    const int m = blockIdx.x;
    const int h = m >> 7, q = (m >> 4) & 7, t = m & 15;
    const int a = t >> 2, b = t & 3;
    gemm_mma(g_B0 + (size_t)((h * 16 + 2 * q) * 4 + a) * MAT2,
             g_B0 + (size_t)((h * 16 + 2 * q + 1) * 4 + b) * MAT2,
             g_B1 + (size_t)m * PLANE, nullptr, 1, q & 1);
}

// Coefficients: c[b, h*128 + q*16 + t] = product of 4 input scalars
__global__ void k_coef(const float* __restrict__ inputs) {
    const int b = blockIdx.x;
    const int tid = threadIdx.x;
    const int h = tid >> 7, q = (tid >> 4) & 7, t = tid & 15;
    const int base = h * 32 + q * 4;
    const float c = inputs[(b * 64 + base + 0) * 2 + ((t >> 3) & 1)]
                  * inputs[(b * 64 + base + 1) * 2 + ((t >> 2) & 1)]
                  * inputs[(b * 64 + base + 2) * 2 + ((t >> 1) & 1)]
                  * inputs[(b * 64 + base + 3) * 2 + (t & 1)];
    g_coef[b * 256 + tid] = c;
}

// Materialize M2[b,hq] = sum_t coef * B1[hq,t]; output hi/lo bf16.
__global__ __launch_bounds__(256)
void k_mat() {
    const int hq = blockIdx.y;
    const int e = (blockIdx.x * 256 + threadIdx.x) * 2;

    __shared__ float sc[NB][16];
    for (int i = threadIdx.x; i < NB * 16; i += 256)
        sc[i >> 4][i & 15] = g_coef[(i >> 4) * 256 + hq * 16 + (i & 15)];
    __syncthreads();

    float2 v[16];
    const float* src = g_B1 + (size_t)hq * 16 * PLANE + e;
#pragma unroll
    for (int t = 0; t < 16; t++) v[t] = *(const float2*)(src + (size_t)t * PLANE);

#pragma unroll 2
    for (int b = 0; b < NB; b++) {
        float s0 = 0.0f, s1 = 0.0f;
#pragma unroll
        for (int t = 0; t < 16; t++) {
            const float c = sc[b][t];
            s0 = fmaf(c, v[t].x, s0);
            s1 = fmaf(c, v[t].y, s1);
        }
        __nv_bfloat162 hh, ll;
        hh.x = __float2bfloat16(s0);
        hh.y = __float2bfloat16(s1);
        ll.x = __float2bfloat16(s0 - __bfloat162float(hh.x));
        ll.y = __float2bfloat16(s1 - __bfloat162float(hh.y));
        __nv_bfloat16* dst = g_M2 + (size_t)(b * 16 + hq) * MAT2 + e;
        *(uint32_t*)dst = *(uint32_t*)&hh;
        *(uint32_t*)(dst + PLANE) = *(uint32_t*)&ll;
    }
}

// Level 2: 1024 matmuls. m = b*8 + h*4 + r; transpose when r odd.
__global__ __launch_bounds__(256)
void k_l2() {
    const int m = blockIdx.x;
    const int b = m >> 3, h = (m >> 2) & 1, r = m & 3;
    gemm_mma(g_M2 + (size_t)(b * 16 + h * 8 + 2 * r) * MAT2,
             g_M2 + (size_t)(b * 16 + h * 8 + 2 * r + 1) * MAT2,
             nullptr, g_L2 + (size_t)m * MAT2, 0, r & 1);
}

// Level 3: 512 matmuls. m = b*4 + h*2 + r; transpose when r odd.
__global__ __launch_bounds__(256)
void k_l3() {
    const int m = blockIdx.x;
    const int b = m >> 2, h = (m >> 1) & 1, r = m & 1;
    gemm_mma(g_L2 + (size_t)(b * 8 + h * 4 + 2 * r) * MAT2,
             g_L2 + (size_t)(b * 8 + h * 4 + 2 * r + 1) * MAT2,
             nullptr, g_L3 + (size_t)m * MAT2, 0, r & 1);
}

// Level 4: 256 matmuls. m = b*2 + h. L (h=0) transposed (B-operand of k_prod).
__global__ __launch_bounds__(256)
void k_l4() {
    const int m = blockIdx.x;
    const int b = m >> 1, h = m & 1;
    gemm_mma(g_L3 + (size_t)(b * 4 + h * 2) * MAT2,
             g_L3 + (size_t)(b * 4 + h * 2 + 1) * MAT2,
             nullptr, g_L4 + (size_t)m * MAT2, 0, h == 0);
}

// P_b = R_b @ L_b (fp32 out, row-major P[k][j])
__global__ __launch_bounds__(256)
void k_prod() {
    const int b = blockIdx.x;
    gemm_mma(g_L4 + (size_t)(b * 2 + 1) * MAT2,
             g_L4 + (size_t)(b * 2 + 0) * MAT2,
             g_P + (size_t)b * PLANE, nullptr, 1, 0);
}

// out[b,c] = sum_{j,k} middle[c,j,k] * P[b,k,j]
__global__ __launch_bounds__(256)
void k_final(const float* __restrict__ middle, float* __restrict__ out) {
    const int b = blockIdx.x;
    const int tid = threadIdx.x;
    float part[NOUT];
#pragma unroll
    for (int c = 0; c < NOUT; c++) part[c] = 0.0f;

    const float* Pb = g_P + (size_t)b * PLANE;
    for (int e = tid; e < PLANE; e += 256) {
        const int k = e >> 7, j = e & 127;
        const float p = Pb[e];
#pragma unroll
        for (int c = 0; c < NOUT; c++)
            part[c] = fmaf(middle[c * PLANE + j * 128 + k], p, part[c]);
    }

    __shared__ float red[256];
#pragma unroll
    for (int c = 0; c < NOUT; c++) {
        red[tid] = part[c];
        __syncthreads();
        for (int s = 128; s > 0; s >>= 1) {
            if (tid < s) red[tid] += red[tid + s];
            __syncthreads();
        }
        if (tid == 0) out[b * NOUT + c] = red[0];
        __syncthreads();
    }
}

// ============================================================================
extern "C" void kernel_launch(void* const* d_in, const int* in_sizes, int n_in,
                              void* d_out, int out_size) {
    const float* inputs = (const float*)d_in[0];  // (128, 64, 2)
    const float* left   = (const float*)d_in[1];  // (2, 32, 128, 128)
    const float* right  = (const float*)d_in[2];  // (2, 32, 128, 128)
    const float* middle = (const float*)d_in[3];  // (10, 128, 128)
    float* out = (float*)d_out;                   // (128, 10)

    cudaFuncSetAttribute(k_basis0, cudaFuncAttributeMaxDynamicSharedMemorySize, SM_BYTES);
    cudaFuncSetAttribute(k_basis1, cudaFuncAttributeMaxDynamicSharedMemorySize, SM_BYTES);
    cudaFuncSetAttribute(k_l2,     cudaFuncAttributeMaxDynamicSharedMemorySize, SM_BYTES);
    cudaFuncSetAttribute(k_l3,     cudaFuncAttributeMaxDynamicSharedMemorySize, SM_BYTES);
    cudaFuncSetAttribute(k_l4,     cudaFuncAttributeMaxDynamicSharedMemorySize, SM_BYTES);
    cudaFuncSetAttribute(k_prod,   cudaFuncAttributeMaxDynamicSharedMemorySize, SM_BYTES);

    k_coef  <<<128, 256>>>(inputs);
    k_conv  <<<128, 256>>>(left, right);
    k_basis0<<<128, 256, SM_BYTES>>>();
    k_basis1<<<256, 256, SM_BYTES>>>();
    k_mat   <<<dim3(32, 16), 256>>>();
    k_l2    <<<1024, 256, SM_BYTES>>>();
    k_l3    <<<512,  256, SM_BYTES>>>();
    k_l4    <<<256,  256, SM_BYTES>>>();
    k_prod  <<<128,  256, SM_BYTES>>>();
    k_final <<<128,  256>>>(middle, out);
}

// round 4
// speedup vs baseline: 1.9295x; 1.2034x over previous
#include <cuda_runtime.h>
#include <cuda_bf16.h>
#include <cstdint>

// MPSLayer: BATCH=128, two halves of 32 sites, D_BOND=128, NOUT=10.
// Basis trick cuts work to 2304 matmuls of 128^3; all run on tensor cores via
// mma.sync m16n8k16 bf16 with a 3-term bf16 hi/lo split, fp32 accumulation:
//   A*B ~= Ahi*Bhi + Ahi*Blo + Alo*Bhi
// mma computes D[m,n] = sum_k A[m,k]*Bst[n,k]; odd-tree-position outputs are
// stored TRANSPOSED by their producer so every GEMM consumes row-major planes.
// This round: cp.async 2-stage K-pipeline + 80B-stride smem (conflict-free
// ldmatrix) -> 80KB smem/CTA -> 2 CTAs/SM, loads overlap compute.

#define D      128
#define NB     128
#define NOUT   10
#define PLANE  16384
#define MAT2   32768      // hi+lo planes in bf16 elements

// ---------------- static scratch ----------------
__device__ __nv_bfloat16 g_Wc[128 * MAT2];     //   8 MB weights (odd sites transposed)
__device__ __nv_bfloat16 g_B0[128 * MAT2];     //   8 MB basis level 0
__device__ float         g_B1[256 * PLANE];    //  16 MB basis level 1 (fp32)
__device__ float         g_coef[NB * 256];     // 128 KB
__device__ __nv_bfloat16 g_M2[2048 * MAT2];    // 128 MB materialized level-1
__device__ __nv_bfloat16 g_L2[1024 * MAT2];    //  64 MB
__device__ __nv_bfloat16 g_L3[512 * MAT2];     //  32 MB
__device__ __nv_bfloat16 g_L4[256 * MAT2];     //  16 MB
__device__ float         g_P [NB * PLANE];     //   8 MB P_b = R_b @ L_b

// ---------------- smem pipeline layout ----------------
// Per stage: 4 planes (Ahi,Alo,Bhi,Blo), each 128 rows x 32 bf16 (64B data)
// stored at 80B row stride (rows 0..7 hit disjoint bank groups -> ldmatrix
// conflict-free). Stage = 40960B, 2 stages = 81920B. Epilogue reuses smem as
// a 128x129 fp32 tile (66048B <= 81920B).
#define RSTRIDE  80
#define PL_SM    (128 * RSTRIDE)     // 10240
#define STAGE_SM (4 * PL_SM)         // 40960
#define SM_BYTES (2 * STAGE_SM)      // 81920

__device__ __forceinline__ uint32_t smem_u32(const void* p) {
    uint32_t a;
    asm("{ .reg .u64 t; cvta.to.shared.u64 t, %1; cvt.u32.u64 %0, t; }" : "=r"(a) : "l"(p));
    return a;
}

#define CP_ASYNC16(dst, src) \
    asm volatile("cp.async.cg.shared.global [%0], [%1], 16;" :: "r"(dst), "l"(src))
#define CP_COMMIT()  asm volatile("cp.async.commit_group;" ::: "memory")
#define CP_WAIT(n)   asm volatile("cp.async.wait_group %0;" :: "n"(n) : "memory")

#define LDM_X4(r0, r1, r2, r3, a)                                              \
    asm volatile("ldmatrix.sync.aligned.m8n8.x4.shared.b16 {%0,%1,%2,%3}, [%4];" \
        : "=r"(r0), "=r"(r1), "=r"(r2), "=r"(r3) : "r"(a))

#define MMA_BF16(d, a, b0, b1)                                                 \
    asm volatile("mma.sync.aligned.m16n8k16.row.col.f32.bf16.bf16.f32 "        \
        "{%0,%1,%2,%3}, {%4,%5,%6,%7}, {%8,%9}, {%0,%1,%2,%3};"                \
        : "+f"((d)[0]), "+f"((d)[1]), "+f"((d)[2]), "+f"((d)[3])               \
        : "r"((a)[0]), "r"((a)[1]), "r"((a)[2]), "r"((a)[3]), "r"(b0), "r"(b1))

// Issue cp.async for K-chunk c (32 cols) of all 4 planes into stage s.
// 2048 x 16B ops, 8 per thread.
__device__ __forceinline__ void load_chunk(
    uint32_t smb, int s,
    const __nv_bfloat16* __restrict__ A, const __nv_bfloat16* __restrict__ B,
    int c, int tid)
{
    const uint32_t stage = smb + s * STAGE_SM;
#pragma unroll
    for (int j = 0; j < 8; j++) {
        const int i = tid + j * 256;
        const int p = i >> 9;            // plane 0..3
        const int idx = i & 511;
        const int r = idx >> 2;          // row 0..127
        const int q = idx & 3;           // 16B chunk within 64B
        const char* base = (p & 2) ? (const char*)B : (const char*)A;
        base += (size_t)(p & 1) * (PLANE * 2);
        const uint32_t dst = stage + p * PL_SM + r * RSTRIDE + q * 16;
        CP_ASYNC16(dst, base + r * 256 + c * 64 + q * 16);
    }
    CP_COMMIT();
}

// ============================================================================
// 128x128x128 tensor-core GEMM, 3-term bf16 split, fp32 accumulate.
// 256 threads = 8 warps; warp tile 32(m) x 64(n) = 2x8 m16n8k16 fragments.
// cp.async 2-stage pipeline over 4 K-chunks of 32.
// mode: 0 = bf16 hi/lo output, 1 = fp32 output. transpose: store C^T.
// ============================================================================
__device__ __forceinline__ void gemm_mma(
    const __nv_bfloat16* __restrict__ A,     // hi plane; lo at +PLANE
    const __nv_bfloat16* __restrict__ B,     // hi plane; lo at +PLANE
    float* __restrict__ Cf_g,
    __nv_bfloat16* __restrict__ Cb_g,
    int mode, int transpose)
{
    extern __shared__ char smem[];
    const uint32_t smb = smem_u32(smem);
    const int tid  = threadIdx.x;
    const int wid  = tid >> 5;
    const int lane = tid & 31;

    const int m0 = (wid & 3) << 5;    // 0,32,64,96
    const int n0 = (wid >> 2) << 6;   // 0,64
    const int lr = lane & 15;         // ldmatrix row within 16-row tile
    const int lk = (lane >> 4) << 4;  // 0 or 16 (byte offset: k-half)

    float acc[2][8][4];
#pragma unroll
    for (int mt = 0; mt < 2; mt++)
#pragma unroll
        for (int nt = 0; nt < 8; nt++)
#pragma unroll
            for (int q = 0; q < 4; q++) acc[mt][nt][q] = 0.0f;

    // prologue: stage chunks 0 and 1
    load_chunk(smb, 0, A, B, 0, tid);
    load_chunk(smb, 1, A, B, 1, tid);

#pragma unroll
    for (int c = 0; c < 4; c++) {
        if (c == 3) { CP_WAIT(0); } else { CP_WAIT(1); }
        __syncthreads();

        const uint32_t st = smb + (c & 1) * STAGE_SM;
        const uint32_t sAhi = st;
        const uint32_t sAlo = st + PL_SM;
        const uint32_t sBhi = st + 2 * PL_SM;
        const uint32_t sBlo = st + 3 * PL_SM;

#pragma unroll
        for (int k16 = 0; k16 < 2; k16++) {
            const uint32_t kb = (uint32_t)(k16 * 32 + lk);
            uint32_t ah[2][4], al[2][4], bh[4][4], bl[4][4];
#pragma unroll
            for (int mt = 0; mt < 2; mt++) {
                const uint32_t ra = (uint32_t)(m0 + mt * 16 + lr) * RSTRIDE + kb;
                LDM_X4(ah[mt][0], ah[mt][1], ah[mt][2], ah[mt][3], sAhi + ra);
                LDM_X4(al[mt][0], al[mt][1], al[mt][2], al[mt][3], sAlo + ra);
            }
#pragma unroll
            for (int np = 0; np < 4; np++) {
                const uint32_t rb = (uint32_t)(n0 + np * 16 + lr) * RSTRIDE + kb;
                LDM_X4(bh[np][0], bh[np][1], bh[np][2], bh[np][3], sBhi + rb);
                LDM_X4(bl[np][0], bl[np][1], bl[np][2], bl[np][3], sBlo + rb);
            }
#pragma unroll
            for (int mt = 0; mt < 2; mt++)
#pragma unroll
                for (int nt = 0; nt < 8; nt++) {
                    const int g = nt >> 1, s = nt & 1;
                    MMA_BF16(acc[mt][nt], ah[mt], bh[g][s], bh[g][s + 2]);
                    MMA_BF16(acc[mt][nt], ah[mt], bl[g][s], bl[g][s + 2]);
                    MMA_BF16(acc[mt][nt], al[mt], bh[g][s], bh[g][s + 2]);
                }
        }
        __syncthreads();   // stage consumed; safe to refill / overwrite
        if (c < 2) load_chunk(smb, c & 1, A, B, c + 2, tid);
    }

    // ---- epilogue: park accum in smem fp32 tile (stride 129), then store ----
    float* Cf = (float*)smem;
    {
        const int cr = lane >> 2;
        const int cc = (lane & 3) << 1;
#pragma unroll
        for (int mt = 0; mt < 2; mt++)
#pragma unroll
            for (int nt = 0; nt < 8; nt++) {
                const int r = m0 + mt * 16 + cr;
                const int c = n0 + nt * 8 + cc;
                Cf[r * 129 + c]           = acc[mt][nt][0];
                Cf[r * 129 + c + 1]       = acc[mt][nt][1];
                Cf[(r + 8) * 129 + c]     = acc[mt][nt][2];
                Cf[(r + 8) * 129 + c + 1] = acc[mt][nt][3];
            }
    }
    __syncthreads();

    for (int i = tid; i < 8192; i += 256) {
        const int e = i << 1;
        const int r = e >> 7, c = e & 127;
        float v0, v1;
        if (transpose) { v0 = Cf[c * 129 + r]; v1 = Cf[(c + 1) * 129 + r]; }
        else           { v0 = Cf[r * 129 + c]; v1 = Cf[r * 129 + c + 1];  }
        if (mode == 1) {
            *(float2*)(Cf_g + e) = make_float2(v0, v1);
        } else {
            __nv_bfloat162 hh, ll;
            hh.x = __float2bfloat16(v0);
            hh.y = __float2bfloat16(v1);
            ll.x = __float2bfloat16(v0 - __bfloat162float(hh.x));
            ll.y = __float2bfloat16(v1 - __bfloat162float(hh.y));
            *(uint32_t*)(Cb_g + e)         = *(uint32_t*)&hh;
            *(uint32_t*)(Cb_g + PLANE + e) = *(uint32_t*)&ll;
        }
    }
}

// ============================================================================
// Level kernels
// ============================================================================

// Convert fp32 weights -> hi/lo bf16; odd sites stored transposed (B-operands).
__global__ __launch_bounds__(256)
void k_conv(const float* __restrict__ left, const float* __restrict__ right) {
    const int m = blockIdx.x;               // h*64 + s*32 + site
    const int h = m >> 6;
    const int s = (m >> 5) & 1;
    const int site = m & 31;
    const float* src = (h ? right : left) + (size_t)(s * 32 + site) * PLANE;
    __nv_bfloat16* dst = g_Wc + (size_t)m * MAT2;
    const bool tr = site & 1;
    for (int e = threadIdx.x; e < PLANE; e += 256) {
        const float v = tr ? src[(e & 127) * 128 + (e >> 7)] : src[e];
        const __nv_bfloat16 hi = __float2bfloat16(v);
        dst[e] = hi;
        dst[PLANE + e] = __float2bfloat16(v - __bfloat162float(hi));
    }
}

// Basis level 0: 128 matmuls. m = h*64 + p*4 + (s0*2+s1); transpose when p odd.
__global__ __launch_bounds__(256, 2)
void k_basis0() {
    const int m = blockIdx.x;
    const int h = m >> 6, p = (m >> 2) & 15, a = m & 3;
    const int s0 = a >> 1, s1 = a & 1;
    gemm_mma(g_Wc + (size_t)(h * 64 + s0 * 32 + 2 * p) * MAT2,
             g_Wc + (size_t)(h * 64 + s1 * 32 + 2 * p + 1) * MAT2,
             nullptr, g_B0 + (size_t)m * MAT2, 0, p & 1);
}

// Basis level 1: 256 matmuls -> fp32, transposed when q odd.
__global__ __launch_bounds__(256, 2)
void k_basis1() {
    const int m = blockIdx.x;
    const int h = m >> 7, q = (m >> 4) & 7, t = m & 15;
    const int a = t >> 2, b = t & 3;
    gemm_mma(g_B0 + (size_t)((h * 16 + 2 * q) * 4 + a) * MAT2,
             g_B0 + (size_t)((h * 16 + 2 * q + 1) * 4 + b) * MAT2,
             g_B1 + (size_t)m * PLANE, nullptr, 1, q & 1);
}

// Coefficients: c[b, h*128 + q*16 + t] = product of 4 input scalars
__global__ void k_coef(const float* __restrict__ inputs) {
    const int b = blockIdx.x;
    const int tid = threadIdx.x;
    const int h = tid >> 7, q = (tid >> 4) & 7, t = tid & 15;
    const int base = h * 32 + q * 4;
    const float c = inputs[(b * 64 + base + 0) * 2 + ((t >> 3) & 1)]
                  * inputs[(b * 64 + base + 1) * 2 + ((t >> 2) & 1)]
                  * inputs[(b * 64 + base + 2) * 2 + ((t >> 1) & 1)]
                  * inputs[(b * 64 + base + 3) * 2 + (t & 1)];
    g_coef[b * 256 + tid] = c;
}

// Materialize M2[b,hq] = sum_t coef * B1[hq,t]; output hi/lo bf16.
__global__ __launch_bounds__(256)
void k_mat() {
    const int hq = blockIdx.y;
    const int e = (blockIdx.x * 256 + threadIdx.x) * 2;

    __shared__ float sc[NB][16];
    for (int i = threadIdx.x; i < NB * 16; i += 256)
        sc[i >> 4][i & 15] = g_coef[(i >> 4) * 256 + hq * 16 + (i & 15)];
    __syncthreads();

    float2 v[16];
    const float* src = g_B1 + (size_t)hq * 16 * PLANE + e;
#pragma unroll
    for (int t = 0; t < 16; t++) v[t] = *(const float2*)(src + (size_t)t * PLANE);

#pragma unroll 2
    for (int b = 0; b < NB; b++) {
        float s0 = 0.0f, s1 = 0.0f;
#pragma unroll
        for (int t = 0; t < 16; t++) {
            const float c = sc[b][t];
            s0 = fmaf(c, v[t].x, s0);
            s1 = fmaf(c, v[t].y, s1);
        }
        __nv_bfloat162 hh, ll;
        hh.x = __float2bfloat16(s0);
        hh.y = __float2bfloat16(s1);
        ll.x = __float2bfloat16(s0 - __bfloat162float(hh.x));
        ll.y = __float2bfloat16(s1 - __bfloat162float(hh.y));
        __nv_bfloat16* dst = g_M2 + (size_t)(b * 16 + hq) * MAT2 + e;
        *(uint32_t*)dst = *(uint32_t*)&hh;
        *(uint32_t*)(dst + PLANE) = *(uint32_t*)&ll;
    }
}

// Level 2: 1024 matmuls. m = b*8 + h*4 + r; transpose when r odd.
__global__ __launch_bounds__(256, 2)
void k_l2() {
    const int m = blockIdx.x;
    const int b = m >> 3, h = (m >> 2) & 1, r = m & 3;
    gemm_mma(g_M2 + (size_t)(b * 16 + h * 8 + 2 * r) * MAT2,
             g_M2 + (size_t)(b * 16 + h * 8 + 2 * r + 1) * MAT2,
             nullptr, g_L2 + (size_t)m * MAT2, 0, r & 1);
}

// Level 3: 512 matmuls. m = b*4 + h*2 + r; transpose when r odd.
__global__ __launch_bounds__(256, 2)
void k_l3() {
    const int m = blockIdx.x;
    const int b = m >> 2, h = (m >> 1) & 1, r = m & 1;
    gemm_mma(g_L2 + (size_t)(b * 8 + h * 4 + 2 * r) * MAT2,
             g_L2 + (size_t)(b * 8 + h * 4 + 2 * r + 1) * MAT2,
             nullptr, g_L3 + (size_t)m * MAT2, 0, r & 1);
}

// Level 4: 256 matmuls. m = b*2 + h. L (h=0) transposed (B-operand of k_prod).
__global__ __launch_bounds__(256, 2)
void k_l4() {
    const int m = blockIdx.x;
    const int b = m >> 1, h = m & 1;
    gemm_mma(g_L3 + (size_t)(b * 4 + h * 2) * MAT2,
             g_L3 + (size_t)(b * 4 + h * 2 + 1) * MAT2,
             nullptr, g_L4 + (size_t)m * MAT2, 0, h == 0);
}

// P_b = R_b @ L_b (fp32 out, row-major P[k][j])
__global__ __launch_bounds__(256, 2)
void k_prod() {
    const int b = blockIdx.x;
    gemm_mma(g_L4 + (size_t)(b * 2 + 1) * MAT2,
             g_L4 + (size_t)(b * 2 + 0) * MAT2,
             g_P + (size_t)b * PLANE, nullptr, 1, 0);
}

// out[b,c] = sum_{j,k} middle[c,j,k] * P[b,k,j]
__global__ __launch_bounds__(256)
void k_final(const float* __restrict__ middle, float* __restrict__ out) {
    const int b = blockIdx.x;
    const int tid = threadIdx.x;
    float part[NOUT];
#pragma unroll
    for (int c = 0; c < NOUT; c++) part[c] = 0.0f;

    const float* Pb = g_P + (size_t)b * PLANE;
    for (int e = tid; e < PLANE; e += 256) {
        const int k = e >> 7, j = e & 127;
        const float p = Pb[e];
#pragma unroll
        for (int c = 0; c < NOUT; c++)
            part[c] = fmaf(middle[c * PLANE + j * 128 + k], p, part[c]);
    }

    __shared__ float red[256];
#pragma unroll
    for (int c = 0; c < NOUT; c++) {
        red[tid] = part[c];
        __syncthreads();
        for (int s = 128; s > 0; s >>= 1) {
            if (tid < s) red[tid] += red[tid + s];
            __syncthreads();
        }
        if (tid == 0) out[b * NOUT + c] = red[0];
        __syncthreads();
    }
}

// ============================================================================
extern "C" void kernel_launch(void* const* d_in, const int* in_sizes, int n_in,
                              void* d_out, int out_size) {
    const float* inputs = (const float*)d_in[0];  // (128, 64, 2)
    const float* left   = (const float*)d_in[1];  // (2, 32, 128, 128)
    const float* right  = (const float*)d_in[2];  // (2, 32, 128, 128)
    const float* middle = (const float*)d_in[3];  // (10, 128, 128)
    float* out = (float*)d_out;                   // (128, 10)

    cudaFuncSetAttribute(k_basis0, cudaFuncAttributeMaxDynamicSharedMemorySize, SM_BYTES);
    cudaFuncSetAttribute(k_basis1, cudaFuncAttributeMaxDynamicSharedMemorySize, SM_BYTES);
    cudaFuncSetAttribute(k_l2,     cudaFuncAttributeMaxDynamicSharedMemorySize, SM_BYTES);
    cudaFuncSetAttribute(k_l3,     cudaFuncAttributeMaxDynamicSharedMemorySize, SM_BYTES);
    cudaFuncSetAttribute(k_l4,     cudaFuncAttributeMaxDynamicSharedMemorySize, SM_BYTES);
    cudaFuncSetAttribute(k_prod,   cudaFuncAttributeMaxDynamicSharedMemorySize, SM_BYTES);

    k_coef  <<<128, 256>>>(inputs);
    k_conv  <<<128, 256>>>(left, right);
    k_basis0<<<128, 256, SM_BYTES>>>();
    k_basis1<<<256, 256, SM_BYTES>>>();
    k_mat   <<<dim3(32, 16), 256>>>();
    k_l2    <<<1024, 256, SM_BYTES>>>();
    k_l3    <<<512,  256, SM_BYTES>>>();
    k_l4    <<<256,  256, SM_BYTES>>>();
    k_prod  <<<128,  256, SM_BYTES>>>();
    k_final <<<128,  256>>>(middle, out);
}